// round 13
// baseline (speedup 1.0000x reference)
#include <cuda_runtime.h>
#include <cuda_fp16.h>
#include <cstdint>

// Deformable attention, single level (L=1), 50x50 feature map.
// value (16, 2500, 8, 32) f32 | loc (16,2000,8,1,4,2) f32 | aw (16,2000,8,1,4) f32
// out (16, 2000, 256) f32
//
// One block (1024 thr) per (b,h). Value slice converted f32->fp16 during the
// smem fill. Row stride PADDED to 80B (2500 x 80 = 200000B): chunk bank-group
// = (5k + sub) mod 8 is uniform over rows k, spreading the 8 gathered rows of
// each LDS.128 across all 8 bank groups (vs 2 groups at 64B stride -> 4-way
// conflicts). Gathers are LDS.128: warp = 8 queries (lane>>2 = query,
// lane&3 = 16B chunk of 8 fp16 channels). Per-point HFMA2 accumulation,
// promoted to packed f32x2 per point; cross-point sums stay f32.

#define FW 50
#define FH 50
#define BS 16
#define QN 2000
#define HN 8
#define DN 32
#define KN (FW * FH)
#define ROWB 80                     // padded smem row stride in bytes
#define SMEM_BYTES (KN * ROWB)      // 200000

__global__ __launch_bounds__(1024, 1)
void deform_attn_kernel(const float4* __restrict__ value4,
                        const float4* __restrict__ loc4,
                        const float4* __restrict__ aw4,
                        float4* __restrict__ out4) {
    extern __shared__ char sraw[];
    uint2* s2 = reinterpret_cast<uint2*>(sraw);               // fill view (8B)
    const uint4* srow = reinterpret_cast<const uint4*>(sraw); // gather view (16B)

    const int bh  = blockIdx.x;          // 0..127
    const int b   = bh >> 3;
    const int h   = bh & (HN - 1);
    const int tid = threadIdx.x;
    const int lane = tid & 31, wib = tid >> 5;
    const int g   = lane >> 2;           // query within warp (0..7)
    const int sub = lane & 3;            // 16B chunk = channels [sub*8, sub*8+8)

    // ---- fill: f32 -> fp16 convert into padded smem rows ----
    const size_t vbase4 = ((size_t)b * KN * HN + h) * (DN / 4);
    for (int i = tid; i < KN * 8; i += 1024) {
        const int k = i >> 3, quad = i & 7;
        float4 v = __ldg(value4 + vbase4 + (size_t)k * (HN * DN / 4) + quad);
        __half2 h01 = __floats2half2_rn(v.x, v.y);
        __half2 h23 = __floats2half2_rn(v.z, v.w);
        uint2 u;
        u.x = *reinterpret_cast<unsigned*>(&h01);
        u.y = *reinterpret_cast<unsigned*>(&h23);
        s2[k * (ROWB / 8) + quad] = u;   // row stride 80B = 10 uint2
    }
    __syncthreads();

    // ---- consume: warp = 8 consecutive queries per iteration ----
    for (int q0 = wib * 8; q0 < QN; q0 += 32 * 8) {
        const int q = q0 + g;
        const int t = (b * QN + q) * HN + h;

        const float4 l01 = __ldg(loc4 + (size_t)t * 2);
        const float4 l23 = __ldg(loc4 + (size_t)t * 2 + 1);
        const float4 a4  = __ldg(aw4 + t);
        const float px[4] = {l01.x, l01.z, l23.x, l23.z};
        const float py[4] = {l01.y, l01.w, l23.y, l23.w};
        const float pa[4] = {a4.x, a4.y, a4.z, a4.w};

        unsigned long long acc2[4] = {0ull, 0ull, 0ull, 0ull};  // 8 ch, f32x2

        #pragma unroll
        for (int p = 0; p < 4; p++) {
            float x = fmaf(px[p], (float)FW, -0.5f);
            float y = fmaf(py[p], (float)FH, -0.5f);
            float xf = floorf(x), yf = floorf(y);
            int x0 = (int)xf, y0 = (int)yf;
            float fx1 = x - xf, fx0 = 1.0f - fx1;
            float fy1 = y - yf, fy0 = 1.0f - fy1;
            float a = pa[p];

            // one-sided validity (loc in [0,1] -> x0,y0 >= -1; x1,y1 <= 50)
            float ax0 = (x0 >= 0)          ? a * fx0 : 0.0f;
            float ax1 = (x0 + 1 <= FW - 1) ? a * fx1 : 0.0f;
            float by0 = (y0 >= 0)          ? fy0 : 0.0f;
            float by1 = (y0 + 1 <= FH - 1) ? fy1 : 0.0f;
            int x0c = max(x0, 0), x1c = min(x0 + 1, FW - 1);
            int y0c = max(y0, 0), y1c = min(y0 + 1, FH - 1);
            int r0 = y0c * FW, r1 = y1c * FW;

            const int   kidx[4] = {r0 + x0c, r0 + x1c, r1 + x0c, r1 + x1c};
            const float wgt [4] = {ax0 * by0, ax1 * by0, ax0 * by1, ax1 * by1};

            // 4 LDS.128: one per corner, serving all 8 queries in the warp.
            // uint4 index = (k*80 + sub*16)/16 = k*5 + sub
            uint4 r[4];
            #pragma unroll
            for (int c = 0; c < 4; c++)
                r[c] = srow[kidx[c] * (ROWB / 16) + sub];

            // per-point fp16 accumulation over the 4 corners
            __half2 hacc0 = __float2half2_rn(0.0f);
            __half2 hacc1 = hacc0, hacc2 = hacc0, hacc3 = hacc0;
            #pragma unroll
            for (int c = 0; c < 4; c++) {
                const __half2 w2 = __float2half2_rn(wgt[c]);
                hacc0 = __hfma2(w2, *reinterpret_cast<__half2*>(&r[c].x), hacc0);
                hacc1 = __hfma2(w2, *reinterpret_cast<__half2*>(&r[c].y), hacc1);
                hacc2 = __hfma2(w2, *reinterpret_cast<__half2*>(&r[c].z), hacc2);
                hacc3 = __hfma2(w2, *reinterpret_cast<__half2*>(&r[c].w), hacc3);
            }

            // promote point partials to f32 and accumulate (packed f32x2)
            const __half2 hs[4] = {hacc0, hacc1, hacc2, hacc3};
            #pragma unroll
            for (int k = 0; k < 4; k++) {
                float2 f = __half22float2(hs[k]);
                unsigned long long pk;
                asm("mov.b64 %0, {%1, %2};" : "=l"(pk) : "f"(f.x), "f"(f.y));
                asm("add.rn.f32x2 %0, %0, %1;" : "+l"(acc2[k]) : "l"(pk));
            }
        }

        // unpack and store: channels [sub*8, sub*8+8), coalesced 128B per query
        float4 o0, o1;
        asm("mov.b64 {%0, %1}, %2;" : "=f"(o0.x), "=f"(o0.y) : "l"(acc2[0]));
        asm("mov.b64 {%0, %1}, %2;" : "=f"(o0.z), "=f"(o0.w) : "l"(acc2[1]));
        asm("mov.b64 {%0, %1}, %2;" : "=f"(o1.x), "=f"(o1.y) : "l"(acc2[2]));
        asm("mov.b64 {%0, %1}, %2;" : "=f"(o1.z), "=f"(o1.w) : "l"(acc2[3]));
        out4[(size_t)t * 8 + sub * 2]     = o0;
        out4[(size_t)t * 8 + sub * 2 + 1] = o1;
    }
}

extern "C" void kernel_launch(void* const* d_in, const int* in_sizes, int n_in,
                              void* d_out, int out_size) {
    const float4* value = (const float4*)d_in[0];
    // d_in[1] = value_spatial_shapes (int64), unused (compile-time 50x50)
    const float4* loc = (const float4*)d_in[2];
    const float4* aw  = (const float4*)d_in[3];
    float4* out = (float4*)d_out;

    cudaFuncSetAttribute(deform_attn_kernel,
                         cudaFuncAttributeMaxDynamicSharedMemorySize, SMEM_BYTES);

    deform_attn_kernel<<<BS * HN, 1024, SMEM_BYTES>>>(value, loc, aw, out);
}

// round 14
// speedup vs baseline: 1.2272x; 1.2272x over previous
#include <cuda_runtime.h>
#include <cuda_fp16.h>
#include <cstdint>

// Deformable attention, single level (L=1), 50x50 feature map.
// value (16, 2500, 8, 32) f32 | loc (16,2000,8,1,4,2) f32 | aw (16,2000,8,1,4) f32
// out (16, 2000, 256) f32
//
// One block (1024 thr) per (b,h). Value slice converted f32->fp16 during the
// smem fill (2500 rows x 64B = 160000B, natural stride -- 80B padding was
// measured WORSE: 16-bank windows at arbitrary 4-bank offsets collide with
// p=7/8 vs 1/2 at {0,16}). Gathers are LDS.128: warp = 8 queries
// (lane>>2 = query, lane&3 = 16B chunk of 8 fp16 channels). Per-point HFMA2
// accumulation promoted to packed f32x2; cross-point sums f32.
// Loc/aw are software-pipelined one q-iteration ahead; corner LDS issue
// before the bilinear weight math.

#define FW 50
#define FH 50
#define BS 16
#define QN 2000
#define HN 8
#define DN 32
#define KN (FW * FH)
#define SMEM_BYTES (KN * DN * 2)   // 160000

__global__ __launch_bounds__(1024, 1)
void deform_attn_kernel(const float4* __restrict__ value4,
                        const float4* __restrict__ loc4,
                        const float4* __restrict__ aw4,
                        float4* __restrict__ out4) {
    extern __shared__ char sraw[];
    uint4* s4u = reinterpret_cast<uint4*>(sraw);              // fill view (16B)
    const uint4* srow = reinterpret_cast<const uint4*>(sraw); // row k = 4 uint4

    const int bh  = blockIdx.x;          // 0..127
    const int b   = bh >> 3;
    const int h   = bh & (HN - 1);
    const int tid = threadIdx.x;
    const int lane = tid & 31, wib = tid >> 5;
    const int g   = lane >> 2;           // query within warp (0..7)
    const int sub = lane & 3;            // 16B chunk = channels [sub*8, sub*8+8)

    // ---- fill: f32 -> fp16, two float4 loads -> one STS.128 ----
    const size_t vbase4 = ((size_t)b * KN * HN + h) * (DN / 4);
    for (int i = tid; i < KN * 4; i += 1024) {
        const int k = i >> 2, quad = i & 3;       // 16B chunk quad of row k
        const size_t src = vbase4 + (size_t)k * (HN * DN / 4) + quad * 2;
        float4 va = __ldg(value4 + src);
        float4 vb = __ldg(value4 + src + 1);
        __half2 h0 = __floats2half2_rn(va.x, va.y);
        __half2 h1 = __floats2half2_rn(va.z, va.w);
        __half2 h2 = __floats2half2_rn(vb.x, vb.y);
        __half2 h3 = __floats2half2_rn(vb.z, vb.w);
        uint4 u;
        u.x = *reinterpret_cast<unsigned*>(&h0);
        u.y = *reinterpret_cast<unsigned*>(&h1);
        u.z = *reinterpret_cast<unsigned*>(&h2);
        u.w = *reinterpret_cast<unsigned*>(&h3);
        s4u[i] = u;
    }
    __syncthreads();

    // ---- consume: warp = 8 consecutive queries; params pipelined 1 ahead ----
    const int t0 = (b * QN + wib * 8 + g) * HN + h;
    float4 l01 = __ldg(loc4 + (size_t)t0 * 2);
    float4 l23 = __ldg(loc4 + (size_t)t0 * 2 + 1);
    float4 a4  = __ldg(aw4 + t0);

    for (int q0 = wib * 8; q0 < QN; q0 += 32 * 8) {
        const int t = (b * QN + q0 + g) * HN + h;

        // consume current params, prefetch next iteration's
        const float px[4] = {l01.x, l01.z, l23.x, l23.z};
        const float py[4] = {l01.y, l01.w, l23.y, l23.w};
        const float pa[4] = {a4.x, a4.y, a4.z, a4.w};
        {
            const int q0n = q0 + 32 * 8;
            const int tn  = (q0n < QN) ? t + 32 * 8 * HN : t;
            l01 = __ldg(loc4 + (size_t)tn * 2);
            l23 = __ldg(loc4 + (size_t)tn * 2 + 1);
            a4  = __ldg(aw4 + tn);
        }

        unsigned long long acc2[4] = {0ull, 0ull, 0ull, 0ull};  // 8 ch, f32x2

        #pragma unroll
        for (int p = 0; p < 4; p++) {
            float x = fmaf(px[p], (float)FW, -0.5f);
            float y = fmaf(py[p], (float)FH, -0.5f);
            float xf = floorf(x), yf = floorf(y);
            int x0 = (int)xf, y0 = (int)yf;

            // indices first -> issue the 4 LDS.128 before weight math
            int x0c = max(x0, 0), x1c = min(x0 + 1, FW - 1);
            int y0c = max(y0, 0), y1c = min(y0 + 1, FH - 1);
            int r0 = y0c * FW, r1 = y1c * FW;
            const int kidx[4] = {r0 + x0c, r0 + x1c, r1 + x0c, r1 + x1c};

            uint4 r[4];
            #pragma unroll
            for (int c = 0; c < 4; c++)
                r[c] = srow[kidx[c] * 4 + sub];

            // weights (one-sided validity: loc in [0,1])
            float fx1 = x - xf, fx0 = 1.0f - fx1;
            float fy1 = y - yf, fy0 = 1.0f - fy1;
            float a = pa[p];
            float ax0 = (x0 >= 0)          ? a * fx0 : 0.0f;
            float ax1 = (x0 + 1 <= FW - 1) ? a * fx1 : 0.0f;
            float by0 = (y0 >= 0)          ? fy0 : 0.0f;
            float by1 = (y0 + 1 <= FH - 1) ? fy1 : 0.0f;
            const float wgt[4] = {ax0 * by0, ax1 * by0, ax0 * by1, ax1 * by1};

            // per-point fp16 accumulation over the 4 corners
            __half2 hacc0 = __float2half2_rn(0.0f);
            __half2 hacc1 = hacc0, hacc2 = hacc0, hacc3 = hacc0;
            #pragma unroll
            for (int c = 0; c < 4; c++) {
                const __half2 w2 = __float2half2_rn(wgt[c]);
                hacc0 = __hfma2(w2, *reinterpret_cast<__half2*>(&r[c].x), hacc0);
                hacc1 = __hfma2(w2, *reinterpret_cast<__half2*>(&r[c].y), hacc1);
                hacc2 = __hfma2(w2, *reinterpret_cast<__half2*>(&r[c].z), hacc2);
                hacc3 = __hfma2(w2, *reinterpret_cast<__half2*>(&r[c].w), hacc3);
            }

            // promote point partials to f32 and accumulate (packed f32x2)
            const __half2 hs[4] = {hacc0, hacc1, hacc2, hacc3};
            #pragma unroll
            for (int k = 0; k < 4; k++) {
                float2 f = __half22float2(hs[k]);
                unsigned long long pk;
                asm("mov.b64 %0, {%1, %2};" : "=l"(pk) : "f"(f.x), "f"(f.y));
                asm("add.rn.f32x2 %0, %0, %1;" : "+l"(acc2[k]) : "l"(pk));
            }
        }

        // unpack and store: channels [sub*8, sub*8+8), coalesced 128B per query
        float4 o0, o1;
        asm("mov.b64 {%0, %1}, %2;" : "=f"(o0.x), "=f"(o0.y) : "l"(acc2[0]));
        asm("mov.b64 {%0, %1}, %2;" : "=f"(o0.z), "=f"(o0.w) : "l"(acc2[1]));
        asm("mov.b64 {%0, %1}, %2;" : "=f"(o1.x), "=f"(o1.y) : "l"(acc2[2]));
        asm("mov.b64 {%0, %1}, %2;" : "=f"(o1.z), "=f"(o1.w) : "l"(acc2[3]));
        out4[(size_t)t * 8 + sub * 2]     = o0;
        out4[(size_t)t * 8 + sub * 2 + 1] = o1;
    }
}

extern "C" void kernel_launch(void* const* d_in, const int* in_sizes, int n_in,
                              void* d_out, int out_size) {
    const float4* value = (const float4*)d_in[0];
    // d_in[1] = value_spatial_shapes (int64), unused (compile-time 50x50)
    const float4* loc = (const float4*)d_in[2];
    const float4* aw  = (const float4*)d_in[3];
    float4* out = (float4*)d_out;

    cudaFuncSetAttribute(deform_attn_kernel,
                         cudaFuncAttributeMaxDynamicSharedMemorySize, SMEM_BYTES);

    deform_attn_kernel<<<BS * HN, 1024, SMEM_BYTES>>>(value, loc, aw, out);
}